// round 16
// baseline (speedup 1.0000x reference)
#include <cuda_runtime.h>
#include <cuda_fp16.h>
#include <cstdint>

#define Bz 2
#define Lz 1024
#define Mz (Bz*Lz)      // 2048
#define DM 768
#define DI 1536
#define DI2 3072
#define DS 16
#define RK 48
#define RKP 64
#define XDB 80
#define NSPK 16         // split-K factor for xdbl GEMM

// ---------------- fp32 scratch ----------------
__device__ __align__(16) float g_xz[Mz*DI2];
__device__ __align__(16) float g_dt[Mz*DI];
__device__ __align__(16) float g_xdp[NSPK*Mz*XDB];   // split-K partials for xdbl
__device__ __align__(16) float2 g_pack2[Mz*DI];      // (W, dtt) only
__device__ __align__(16) float g_knq[Mz*48];
__device__ __align__(16) float g_xact[Mz*DI];        // conv+silu(x), fp32

// ---------------- fp16 GEMM operands ----------------
__device__ __align__(16) __half g_hs_c[Mz*DM];
__device__ __align__(16) __half g_ipw_c[DI2*DM];
__device__ __align__(16) __half g_xact_c[Mz*DI];
__device__ __align__(16) __half g_xpw_c[XDB*DI];
__device__ __align__(16) __half g_dtl_c[Mz*RKP];
__device__ __align__(16) __half g_dthw_c[DI*RKP];
__device__ __align__(16) __half g_yg_c[Mz*DI];
__device__ __align__(16) __half g_opw_c[DM*DI];

// ---------------- helpers ----------------
__device__ __forceinline__ void ldsm4(uint32_t& r0, uint32_t& r1, uint32_t& r2, uint32_t& r3,
                                      uint32_t saddr) {
    asm volatile("ldmatrix.sync.aligned.m8n8.x4.shared.b16 {%0,%1,%2,%3}, [%4];"
                 : "=r"(r0), "=r"(r1), "=r"(r2), "=r"(r3) : "r"(saddr));
}
__device__ __forceinline__ void mma_f16(float* c, const uint32_t* a, const uint32_t* b) {
    asm volatile(
        "mma.sync.aligned.m16n8k16.row.col.f32.f16.f16.f32 "
        "{%0,%1,%2,%3}, {%4,%5,%6,%7}, {%8,%9}, {%0,%1,%2,%3};"
        : "+f"(c[0]), "+f"(c[1]), "+f"(c[2]), "+f"(c[3])
        : "r"(a[0]), "r"(a[1]), "r"(a[2]), "r"(a[3]), "r"(b[0]), "r"(b[1]));
}
__device__ __forceinline__ void cpa16(uint32_t dst, const void* src, uint32_t sz) {
    asm volatile("cp.async.cg.shared.global [%0], [%1], 16, %2;" :: "r"(dst), "l"(src), "r"(sz));
}
__device__ __forceinline__ void cpa16u(uint32_t dst, const void* src) {
    asm volatile("cp.async.cg.shared.global [%0], [%1], 16;" :: "r"(dst), "l"(src));
}
__device__ __forceinline__ void cp_commit() { asm volatile("cp.async.commit_group;"); }

// ================= fused fp16-convert kernel (5 segments; seg 4 = pad 48->64) =================
__global__ __launch_bounds__(256)
void cvt5_kernel(const float* __restrict__ s0, __half* __restrict__ o0, int n0, int b0,
                 const float* __restrict__ s1, __half* __restrict__ o1, int n1, int b1,
                 const float* __restrict__ s2, __half* __restrict__ o2, int n2, int b2,
                 const float* __restrict__ s3, __half* __restrict__ o3, int n3, int b3,
                 const float* __restrict__ s4, __half* __restrict__ o4, int n4) {
    int blk = blockIdx.x;
    if (blk >= b3) {
        int i = (blk - b3) * 256 + threadIdx.x;
        if (i < n4) {
            int r = i >> 6, c = i & 63;   // RKP = 64
            float v = (c < RK) ? s4[(size_t)r * RK + c] : 0.f;
            o4[i] = __float2half_rn(v);
        }
        return;
    }
    const float* src; __half* dst; int n, i;
    if (blk < b0)      { src = s0; dst = o0; n = n0; i = blk * 256 + threadIdx.x; }
    else if (blk < b1) { src = s1; dst = o1; n = n1; i = (blk - b0) * 256 + threadIdx.x; }
    else if (blk < b2) { src = s2; dst = o2; n = n2; i = (blk - b1) * 256 + threadIdx.x; }
    else               { src = s3; dst = o3; n = n3; i = (blk - b2) * 256 + threadIdx.x; }
    if (i < n) dst[i] = __float2half_rn(src[i]);
}

// ================= fp16 3-stage swizzled GEMM: C[M,N] = A[M,K] * B[N,K]^T =================
__global__ __launch_bounds__(256, 2)
void mma_gemm(const __half* __restrict__ A, const __half* __restrict__ B,
              float* __restrict__ C, int N, int Kc, int Ktot, int ldc, int partStride) {
    extern __shared__ __align__(16) ushort smbuf[];
    int tid = threadIdx.x, wid = tid >> 5, lane = tid & 31;
    int row0 = blockIdx.y << 7, col0 = blockIdx.x << 7;
    int wm = (wid >> 2) << 6, wn = (wid & 3) << 5;
    int koff = blockIdx.z * Kc;
    C += (size_t)blockIdx.z * partStride;
    uint32_t sbase = (uint32_t)__cvta_generic_to_shared(smbuf);
    bool wActive = (col0 + wn) < N;

    int c0 = tid, c1 = tid + 256;
    int r0 = c0 >> 2, ch0 = c0 & 3, o0 = ch0 << 3;
    int r1 = c1 >> 2, ch1 = c1 & 3, o1 = ch1 << 3;
    int br0 = col0 + r0, br1 = col0 + r1;
    uint32_t s0 = br0 < N ? 16u : 0u, s1 = br1 < N ? 16u : 0u;
    size_t a0b = (size_t)(row0 + r0) * Ktot + koff + o0;
    size_t a1b = (size_t)(row0 + r1) * Ktot + koff + o1;
    size_t b0b = (size_t)(br0 < N ? br0 : 0) * Ktot + koff + o0;
    size_t b1b = (size_t)(br1 < N ? br1 : 0) * Ktot + koff + o1;
    uint32_t d0 = (uint32_t)(r0 * 64 + ((ch0 ^ ((r0 >> 1) & 3)) << 4));
    uint32_t d1 = (uint32_t)(r1 * 64 + ((ch1 ^ ((r1 >> 1) & 3)) << 4));

    uint32_t swa = (uint32_t)(((lane & 15) >> 1) & 3);
    uint32_t cgA = (uint32_t)(lane >> 4);
    uint32_t aRow = (uint32_t)((wm + (lane & 15)) * 64);
    uint32_t swb = (uint32_t)(((lane & 7) >> 1) & 3);
    uint32_t cgB = (uint32_t)((lane >> 3) & 1);
    uint32_t bRow = (uint32_t)((wn + ((lane >> 4) << 3) + (lane & 7)) * 64);

    float acc[4][4][4];
#pragma unroll
    for (int i = 0; i < 4; i++)
#pragma unroll
        for (int j = 0; j < 4; j++)
#pragma unroll
            for (int r = 0; r < 4; r++) acc[i][j][r] = 0.f;

    int niter = Kc >> 5;

    auto issue = [&](int s) {
        uint32_t sb = sbase + (uint32_t)((s % 3) * 16384);
        int ko = s << 5;
        cpa16(sb + d0,        A + a0b + ko, 16);
        cpa16(sb + d1,        A + a1b + ko, 16);
        cpa16(sb + 8192 + d0, B + b0b + ko, s0);
        cpa16(sb + 8192 + d1, B + b1b + ko, s1);
    };

    issue(0); cp_commit();
    if (niter > 1) { issue(1); cp_commit(); }

    for (int it = 0; it < niter; it++) {
        if (it + 1 < niter) asm volatile("cp.async.wait_group 1;");
        else                asm volatile("cp.async.wait_group 0;");
        __syncthreads();
        if (it + 2 < niter) { issue(it + 2); cp_commit(); }

        if (wActive) {
            uint32_t stg = sbase + (uint32_t)((it % 3) * 16384);
#pragma unroll
            for (int kk = 0; kk < 2; kk++) {
                uint32_t ca = ((((uint32_t)(kk << 1) + cgA) ^ swa) << 4);
                uint32_t cb = ((((uint32_t)(kk << 1) + cgB) ^ swb) << 4);
                uint32_t a[4][4], bf[4][2];
#pragma unroll
                for (int mt = 0; mt < 4; mt++)
                    ldsm4(a[mt][0], a[mt][1], a[mt][2], a[mt][3],
                          stg + aRow + (uint32_t)(mt * 1024) + ca);
#pragma unroll
                for (int g = 0; g < 2; g++) {
                    uint32_t q0, q1, q2, q3;
                    ldsm4(q0, q1, q2, q3, stg + 8192 + bRow + (uint32_t)(g * 1024) + cb);
                    bf[2 * g][0] = q0; bf[2 * g][1] = q1;
                    bf[2 * g + 1][0] = q2; bf[2 * g + 1][1] = q3;
                }
#pragma unroll
                for (int mt = 0; mt < 4; mt++)
#pragma unroll
                    for (int ng = 0; ng < 4; ng++) mma_f16(acc[mt][ng], a[mt], bf[ng]);
            }
        }
    }

    int cr = lane >> 2, cc = (lane & 3) << 1;
#pragma unroll
    for (int mt = 0; mt < 4; mt++)
#pragma unroll
        for (int ng = 0; ng < 4; ng++) {
            int row = row0 + wm + (mt << 4) + cr;
            int col = col0 + wn + (ng << 3) + cc;
            if (col < N) {
                *reinterpret_cast<float2*>(C + (size_t)row * ldc + col) =
                    make_float2(acc[mt][ng][0], acc[mt][ng][1]);
                *reinterpret_cast<float2*>(C + (size_t)(row + 8) * ldc + col) =
                    make_float2(acc[mt][ng][2], acc[mt][ng][3]);
            }
        }
}

// ================= xdbl split-K reduce + scatter (knq + dtl convert/pad) =================
__global__ __launch_bounds__(256)
void xdbl_reduce_kernel() {
    int i = blockIdx.x * 256 + threadIdx.x;
    if (i >= Mz * 96) return;
    int r = i / 96, c = i - r * 96;
    if (c < 48) {
        float v = 0.f;
#pragma unroll
        for (int z = 0; z < NSPK; z++) v += g_xdp[(size_t)z * Mz * XDB + (size_t)r * XDB + c];
        g_dtl_c[(size_t)r * RKP + c] = __float2half_rn(v);
    } else if (c < 64) {
        g_dtl_c[(size_t)r * RKP + c] = __float2half_rn(0.f);
    } else if (c < 80) {
        int sc = c - 16;
        float v = 0.f;
#pragma unroll
        for (int z = 0; z < NSPK; z++) v += g_xdp[(size_t)z * Mz * XDB + (size_t)r * XDB + sc];
        g_knq[(size_t)r * 48 + (c - 64)] = v;
        g_knq[(size_t)r * 48 + 16 + (c - 64)] = v * v;
    } else {
        int sc = c - 16;
        float v = 0.f;
#pragma unroll
        for (int z = 0; z < NSPK; z++) v += g_xdp[(size_t)z * Mz * XDB + (size_t)r * XDB + sc];
        g_knq[(size_t)r * 48 + 32 + (c - 80)] = v;
    }
}

// ================= depthwise causal conv (k=4) + SiLU -> fp32 + fp16 =================
__global__ __launch_bounds__(128)
void conv_silu_kernel(const float* __restrict__ conv_w,
                      const float* __restrict__ conv_b) {
    int d = blockIdx.x * 128 + threadIdx.x;
    int t0 = blockIdx.y * 16;
    int b = blockIdx.z;
    size_t base = (size_t)b * Lz;

    float xv[19];
#pragma unroll
    for (int i = 0; i < 19; i++) {
        int t = t0 - 3 + i;
        xv[i] = (t >= 0) ? g_xz[(base + t) * DI2 + d] : 0.f;
    }
    float w0 = conv_w[d * 4 + 0], w1 = conv_w[d * 4 + 1];
    float w2 = conv_w[d * 4 + 2], w3 = conv_w[d * 4 + 3];
    float bias = conv_b[d];
#pragma unroll
    for (int j = 0; j < 16; j++) {
        float a = fmaf(w0, xv[j], fmaf(w1, xv[j + 1], fmaf(w2, xv[j + 2], fmaf(w3, xv[j + 3], bias))));
        float s = a / (1.f + __expf(-a));
        size_t idx = (base + t0 + j) * DI + d;
        g_xact[idx] = s;
        g_xact_c[idx] = __float2half_rn(s);
    }
}

// ================= prep: rank-1 Newton-Schulz + (W, dtt) float2 pack =================
__global__ __launch_bounds__(256)
void prep_kernel(const float* __restrict__ dt_bias) {
    int m = blockIdx.x;
    int tid = threadIdx.x;
    __shared__ float s_ksq[16];
    __shared__ float s_kk, s_su;
    __shared__ float red[8];

    if (tid < 16) s_ksq[tid] = g_knq[(size_t)m * 48 + 16 + tid];
    __syncthreads();
    if (tid == 0) {
        float kk = 0.f;
#pragma unroll
        for (int n = 0; n < 16; n++) kk += s_ksq[n];
        s_kk = kk;
    }
    __syncthreads();
    float kk = s_kk;

    float u[6], dtt[6];
    float su = 0.f;
#pragma unroll
    for (int i = 0; i < 6; i++) {
        int d = tid + i * 256;
        float dtr = g_dt[(size_t)m * DI + d] + dt_bias[d];
        float s0 = 1.f / (1.f + __expf(-dtr));
        float dv = s0 / (1.f + s0 * kk);
        float x = g_xact[(size_t)m * DI + d];
        float uu = dv * x;
        su += uu * uu;
        u[i] = uu; dtt[i] = dv;
    }
#pragma unroll
    for (int off = 16; off > 0; off >>= 1) su += __shfl_xor_sync(0xffffffffu, su, off);
    if ((tid & 31) == 0) red[tid >> 5] = su;
    __syncthreads();
    if (tid == 0) {
        float s = 0.f;
#pragma unroll
        for (int i = 0; i < 8; i++) s += red[i];
        s_su = s;
    }
    __syncthreads();

    float Nn = sqrtf(s_su * kk);
    float t1 = 1.f / (Nn + 1e-7f);
    float nt = Nn * t1;
    float nt2 = nt * nt;
    float s = t1 * (3.4445f + nt2 * (-4.7750f + 2.0315f * nt2));

#pragma unroll
    for (int i = 0; i < 6; i++) {
        int d = tid + i * 256;
        g_pack2[(size_t)m * DI + d] = make_float2(s * u[i], dtt[i]);
    }
}

// ================= scan: 4-way n-split; float2 pack + direct x/z; 4-stage cp.async =================
__global__ __launch_bounds__(64)
void scan_kernel(const float* __restrict__ Dv) {
    __shared__ __align__(16) float2 s_pA[4][128];
    __shared__ __align__(16) float  s_x[4][128];
    __shared__ __align__(16) float  s_z[4][128];
    __shared__ __align__(16) float  s_knq[4][384];
    int tid = threadIdx.x;
    int ng = tid & 3, dd = tid >> 2;
    int d0 = blockIdx.x << 4;
    int d = d0 + dd;
    int b = blockIdx.y;
    size_t mbase = (size_t)b * Lz;
    const int NW = Lz / 8;

    uint32_t ppA  = (uint32_t)__cvta_generic_to_shared(s_pA);
    uint32_t px   = (uint32_t)__cvta_generic_to_shared(s_x);
    uint32_t pz   = (uint32_t)__cvta_generic_to_shared(s_z);
    uint32_t pknq = (uint32_t)__cvta_generic_to_shared(s_knq);
    const float* knq_src = g_knq + mbase * 48;
    float D_d = Dv[d];

    auto issue = [&](int w) {
        uint32_t st = (uint32_t)(w & 3);
        size_t m0 = mbase + ((size_t)w << 3);
        // packA: 64 chunks of 16B (2 float2 each)
        {
            int c = tid;
            int s = c >> 3, dd2 = (c & 7) << 1;
            cpa16u(ppA + st * 1024 + (uint32_t)(c << 4),
                   &g_pack2[(m0 + s) * DI + d0 + dd2]);
        }
        // x: 32 chunks; z: 32 chunks (threads 32..63)
        if (tid < 32) {
            int s = tid >> 2, dd2 = (tid & 3) << 2;
            cpa16u(px + st * 512 + (uint32_t)(tid << 4),
                   g_xact + (m0 + s) * DI + d0 + dd2);
        } else {
            int c = tid - 32;
            int s = c >> 2, dd2 = (c & 3) << 2;
            cpa16u(pz + st * 512 + (uint32_t)(c << 4),
                   g_xz + (m0 + s) * DI2 + DI + d0 + dd2);
        }
        // knq: 96 chunks
#pragma unroll
        for (int i = 0; i < 2; i++) {
            int c = tid + (i << 6);
            if (c < 96)
                cpa16u(pknq + st * 1536 + (uint32_t)(c << 4),
                       knq_src + (((size_t)w << 3) * 48) + (c << 2));
        }
    };

    issue(0); cp_commit();
    issue(1); cp_commit();
    issue(2); cp_commit();

    float v0 = 0.f, v1 = 0.f, v2 = 0.f, v3 = 0.f;
    float h0 = 0.f, h1 = 0.f, h2 = 0.f, h3 = 0.f;

    for (int w = 0; w < NW; w++) {
        asm volatile("cp.async.wait_group 2;");
        __syncthreads();
        if (w + 3 < NW) issue(w + 3);
        cp_commit();

        int st = w & 3;
        float ys[8];
#pragma unroll
        for (int s = 0; s < 8; s++) {
            float2 p = s_pA[st][(s << 4) + dd];
            const float* kb = &s_knq[st][s * 48 + (ng << 2)];
            float4 kv = *reinterpret_cast<const float4*>(kb);
            float4 k2 = *reinterpret_cast<const float4*>(kb + 16);
            float4 qv = *reinterpret_cast<const float4*>(kb + 32);
            v0 = fmaf(0.9f, v0, p.x * kv.x); h0 = fmaf(fmaf(-p.y, k2.x, 1.f), h0, v0);
            v1 = fmaf(0.9f, v1, p.x * kv.y); h1 = fmaf(fmaf(-p.y, k2.y, 1.f), h1, v1);
            v2 = fmaf(0.9f, v2, p.x * kv.z); h2 = fmaf(fmaf(-p.y, k2.z, 1.f), h2, v2);
            v3 = fmaf(0.9f, v3, p.x * kv.w); h3 = fmaf(fmaf(-p.y, k2.w, 1.f), h3, v3);
            ys[s] = fmaf(h0, qv.x, fmaf(h1, qv.y, fmaf(h2, qv.z, h3 * qv.w)));
        }
#pragma unroll
        for (int s = 0; s < 8; s++) ys[s] += __shfl_xor_sync(0xffffffffu, ys[s], 1);
#pragma unroll
        for (int s = 0; s < 8; s++) ys[s] += __shfl_xor_sync(0xffffffffu, ys[s], 2);
        if (ng == 0) {
#pragma unroll
            for (int s = 0; s < 8; s++) {
                float xv = s_x[st][(s << 4) + dd];
                float zv = s_z[st][(s << 4) + dd];
                float zs = zv / (1.f + __expf(-zv));
                size_t m = mbase + ((size_t)w << 3) + s;
                float yo = (ys[s] + D_d * xv) * zs;
                g_yg_c[m * DI + d] = __float2half_rn(yo);
            }
        }
    }
}

// ================= launch =================
extern "C" void kernel_launch(void* const* d_in, const int* in_sizes, int n_in,
                              void* d_out, int out_size) {
    const float* hs        = (const float*)d_in[0];
    const float* in_proj_w = (const float*)d_in[1];
    const float* conv_w    = (const float*)d_in[2];
    const float* conv_b    = (const float*)d_in[3];
    const float* x_proj_w  = (const float*)d_in[4];
    const float* dt_head_w = (const float*)d_in[5];
    const float* dt_head_b = (const float*)d_in[6];
    const float* out_proj  = (const float*)d_in[7];
    const float* Dv        = (const float*)d_in[8];
    float* out = (float*)d_out;

    static bool attr_set = false;
    if (!attr_set) {
        cudaFuncSetAttribute(mma_gemm, cudaFuncAttributeMaxDynamicSharedMemorySize, 49152);
        attr_set = true;
    }
    const int SMEMB = 49152;   // 3 stages x 16KB

    void *p_xz, *p_dt, *p_xdp;
    cudaGetSymbolAddress(&p_xz, g_xz);
    cudaGetSymbolAddress(&p_dt, g_dt);
    cudaGetSymbolAddress(&p_xdp, g_xdp);
    void *hs_c, *ipw_c, *xact_c, *xpw_c, *dtl_c, *dthw_c, *yg_c, *opw_c;
    cudaGetSymbolAddress(&hs_c, g_hs_c);
    cudaGetSymbolAddress(&ipw_c, g_ipw_c);
    cudaGetSymbolAddress(&xact_c, g_xact_c);
    cudaGetSymbolAddress(&xpw_c, g_xpw_c);
    cudaGetSymbolAddress(&dtl_c, g_dtl_c);
    cudaGetSymbolAddress(&dthw_c, g_dthw_c);
    cudaGetSymbolAddress(&yg_c, g_yg_c);
    cudaGetSymbolAddress(&opw_c, g_opw_c);

    // 0) fused fp16 converts: hs, in_proj_w, x_proj_w, out_proj, dt_head_w(pad)
    {
        int n0 = Mz * DM, n1 = DI2 * DM, n2 = XDB * DI, n3 = DM * DI, n4 = DI * RKP;
        int g0 = (n0 + 255) / 256, g1 = (n1 + 255) / 256, g2 = (n2 + 255) / 256,
            g3 = (n3 + 255) / 256, g4 = (n4 + 255) / 256;
        cvt5_kernel<<<g0 + g1 + g2 + g3 + g4, 256>>>(
            hs, (__half*)hs_c, n0, g0,
            in_proj_w, (__half*)ipw_c, n1, g0 + g1,
            x_proj_w, (__half*)xpw_c, n2, g0 + g1 + g2,
            out_proj, (__half*)opw_c, n3, g0 + g1 + g2 + g3,
            dt_head_w, (__half*)dthw_c, n4);
    }

    // 1) xz = hs @ in_proj^T  (2048 x 3072, K=768)
    mma_gemm<<<dim3(DI2 / 128, Mz / 128, 1), 256, SMEMB>>>(
        (const __half*)hs_c, (const __half*)ipw_c, (float*)p_xz, DI2, DM, DM, DI2, 0);
    // 2) conv + SiLU
    conv_silu_kernel<<<dim3(DI / 128, Lz / 16, Bz), 128>>>(conv_w, conv_b);
    // 3) x_dbl split-K partials (16-way)
    mma_gemm<<<dim3(1, Mz / 128, NSPK), 256, SMEMB>>>(
        (const __half*)xact_c, (const __half*)xpw_c, (float*)p_xdp,
        XDB, DI / NSPK, DI, XDB, Mz * XDB);
    // 3b) reduce -> knq + dtl
    xdbl_reduce_kernel<<<(Mz * 96 + 255) / 256, 256>>>();
    // 4) dt = dt_low @ dt_head^T  (K=64 padded)
    mma_gemm<<<dim3(DI / 128, Mz / 128, 1), 256, SMEMB>>>(
        (const __half*)dtl_c, (const __half*)dthw_c, (float*)p_dt, DI, RKP, RKP, DI, 0);
    // 5) prep (float2 pack)
    prep_kernel<<<Mz, 256>>>(dt_head_b);
    // 6) scan
    scan_kernel<<<dim3(DI / 16, Bz), 64>>>(Dv);
    // 7) out = yg @ out_proj^T
    mma_gemm<<<dim3(DM / 128, Mz / 128, 1), 256, SMEMB>>>(
        (const __half*)yg_c, (const __half*)opw_c, out, DM, DI, DI, DM, 0);
}

// round 17
// speedup vs baseline: 1.3512x; 1.3512x over previous
#include <cuda_runtime.h>
#include <cuda_fp16.h>
#include <cstdint>

#define Bz 2
#define Lz 1024
#define Mz (Bz*Lz)      // 2048
#define DM 768
#define DI 1536
#define DI2 3072
#define DS 16
#define RK 48
#define RKP 64
#define XDB 80
#define NSPK 16         // split-K factor for xdbl GEMM

// ---------------- fp32 scratch ----------------
__device__ __align__(16) float g_xz[Mz*DI2];
__device__ __align__(16) float g_dt[Mz*DI];
__device__ __align__(16) float g_xdp[NSPK*Mz*XDB];   // split-K partials for xdbl
__device__ float4 g_pack[Mz*DI];                     // (W, dtt, D*x, silu z)
__device__ __align__(16) float g_knq[Mz*48];
__device__ __align__(16) float g_xact[Mz*DI];        // conv+silu(x), fp32

// ---------------- fp16 GEMM operands ----------------
__device__ __align__(16) __half g_hs_c[Mz*DM];
__device__ __align__(16) __half g_ipw_c[DI2*DM];
__device__ __align__(16) __half g_xact_c[Mz*DI];
__device__ __align__(16) __half g_xpw_c[XDB*DI];
__device__ __align__(16) __half g_dtl_c[Mz*RKP];
__device__ __align__(16) __half g_dthw_c[DI*RKP];
__device__ __align__(16) __half g_yg_c[Mz*DI];
__device__ __align__(16) __half g_opw_c[DM*DI];

// ---------------- helpers ----------------
__device__ __forceinline__ void ldsm4(uint32_t& r0, uint32_t& r1, uint32_t& r2, uint32_t& r3,
                                      uint32_t saddr) {
    asm volatile("ldmatrix.sync.aligned.m8n8.x4.shared.b16 {%0,%1,%2,%3}, [%4];"
                 : "=r"(r0), "=r"(r1), "=r"(r2), "=r"(r3) : "r"(saddr));
}
__device__ __forceinline__ void mma_f16(float* c, const uint32_t* a, const uint32_t* b) {
    asm volatile(
        "mma.sync.aligned.m16n8k16.row.col.f32.f16.f16.f32 "
        "{%0,%1,%2,%3}, {%4,%5,%6,%7}, {%8,%9}, {%0,%1,%2,%3};"
        : "+f"(c[0]), "+f"(c[1]), "+f"(c[2]), "+f"(c[3])
        : "r"(a[0]), "r"(a[1]), "r"(a[2]), "r"(a[3]), "r"(b[0]), "r"(b[1]));
}
__device__ __forceinline__ void cpa16(uint32_t dst, const void* src, uint32_t sz) {
    asm volatile("cp.async.cg.shared.global [%0], [%1], 16, %2;" :: "r"(dst), "l"(src), "r"(sz));
}
__device__ __forceinline__ void cpa16u(uint32_t dst, const void* src) {
    asm volatile("cp.async.cg.shared.global [%0], [%1], 16;" :: "r"(dst), "l"(src));
}
__device__ __forceinline__ void cp_commit() { asm volatile("cp.async.commit_group;"); }

// ================= fused fp16-convert kernel (5 segments; seg 4 = pad 48->64) =================
__global__ __launch_bounds__(256)
void cvt5_kernel(const float* __restrict__ s0, __half* __restrict__ o0, int n0, int b0,
                 const float* __restrict__ s1, __half* __restrict__ o1, int n1, int b1,
                 const float* __restrict__ s2, __half* __restrict__ o2, int n2, int b2,
                 const float* __restrict__ s3, __half* __restrict__ o3, int n3, int b3,
                 const float* __restrict__ s4, __half* __restrict__ o4, int n4) {
    int blk = blockIdx.x;
    if (blk >= b3) {
        int i = (blk - b3) * 256 + threadIdx.x;
        if (i < n4) {
            int r = i >> 6, c = i & 63;   // RKP = 64
            float v = (c < RK) ? s4[(size_t)r * RK + c] : 0.f;
            o4[i] = __float2half_rn(v);
        }
        return;
    }
    const float* src; __half* dst; int n, i;
    if (blk < b0)      { src = s0; dst = o0; n = n0; i = blk * 256 + threadIdx.x; }
    else if (blk < b1) { src = s1; dst = o1; n = n1; i = (blk - b0) * 256 + threadIdx.x; }
    else if (blk < b2) { src = s2; dst = o2; n = n2; i = (blk - b1) * 256 + threadIdx.x; }
    else               { src = s3; dst = o3; n = n3; i = (blk - b2) * 256 + threadIdx.x; }
    if (i < n) dst[i] = __float2half_rn(src[i]);
}

// ================= fp16 3-stage swizzled GEMM: C[M,N] = A[M,K] * B[N,K]^T =================
__global__ __launch_bounds__(256, 2)
void mma_gemm(const __half* __restrict__ A, const __half* __restrict__ B,
              float* __restrict__ C, int N, int Kc, int Ktot, int ldc, int partStride) {
    extern __shared__ __align__(16) ushort smbuf[];
    int tid = threadIdx.x, wid = tid >> 5, lane = tid & 31;
    int row0 = blockIdx.y << 7, col0 = blockIdx.x << 7;
    int wm = (wid >> 2) << 6, wn = (wid & 3) << 5;
    int koff = blockIdx.z * Kc;
    C += (size_t)blockIdx.z * partStride;
    uint32_t sbase = (uint32_t)__cvta_generic_to_shared(smbuf);
    bool wActive = (col0 + wn) < N;

    int c0 = tid, c1 = tid + 256;
    int r0 = c0 >> 2, ch0 = c0 & 3, o0 = ch0 << 3;
    int r1 = c1 >> 2, ch1 = c1 & 3, o1 = ch1 << 3;
    int br0 = col0 + r0, br1 = col0 + r1;
    uint32_t s0 = br0 < N ? 16u : 0u, s1 = br1 < N ? 16u : 0u;
    size_t a0b = (size_t)(row0 + r0) * Ktot + koff + o0;
    size_t a1b = (size_t)(row0 + r1) * Ktot + koff + o1;
    size_t b0b = (size_t)(br0 < N ? br0 : 0) * Ktot + koff + o0;
    size_t b1b = (size_t)(br1 < N ? br1 : 0) * Ktot + koff + o1;
    uint32_t d0 = (uint32_t)(r0 * 64 + ((ch0 ^ ((r0 >> 1) & 3)) << 4));
    uint32_t d1 = (uint32_t)(r1 * 64 + ((ch1 ^ ((r1 >> 1) & 3)) << 4));

    uint32_t swa = (uint32_t)(((lane & 15) >> 1) & 3);
    uint32_t cgA = (uint32_t)(lane >> 4);
    uint32_t aRow = (uint32_t)((wm + (lane & 15)) * 64);
    uint32_t swb = (uint32_t)(((lane & 7) >> 1) & 3);
    uint32_t cgB = (uint32_t)((lane >> 3) & 1);
    uint32_t bRow = (uint32_t)((wn + ((lane >> 4) << 3) + (lane & 7)) * 64);

    float acc[4][4][4];
#pragma unroll
    for (int i = 0; i < 4; i++)
#pragma unroll
        for (int j = 0; j < 4; j++)
#pragma unroll
            for (int r = 0; r < 4; r++) acc[i][j][r] = 0.f;

    int niter = Kc >> 5;

    auto issue = [&](int s) {
        uint32_t sb = sbase + (uint32_t)((s % 3) * 16384);
        int ko = s << 5;
        cpa16(sb + d0,        A + a0b + ko, 16);
        cpa16(sb + d1,        A + a1b + ko, 16);
        cpa16(sb + 8192 + d0, B + b0b + ko, s0);
        cpa16(sb + 8192 + d1, B + b1b + ko, s1);
    };

    issue(0); cp_commit();
    if (niter > 1) { issue(1); cp_commit(); }

    for (int it = 0; it < niter; it++) {
        if (it + 1 < niter) asm volatile("cp.async.wait_group 1;");
        else                asm volatile("cp.async.wait_group 0;");
        __syncthreads();
        if (it + 2 < niter) { issue(it + 2); cp_commit(); }

        if (wActive) {
            uint32_t stg = sbase + (uint32_t)((it % 3) * 16384);
#pragma unroll
            for (int kk = 0; kk < 2; kk++) {
                uint32_t ca = ((((uint32_t)(kk << 1) + cgA) ^ swa) << 4);
                uint32_t cb = ((((uint32_t)(kk << 1) + cgB) ^ swb) << 4);
                uint32_t a[4][4], bf[4][2];
#pragma unroll
                for (int mt = 0; mt < 4; mt++)
                    ldsm4(a[mt][0], a[mt][1], a[mt][2], a[mt][3],
                          stg + aRow + (uint32_t)(mt * 1024) + ca);
#pragma unroll
                for (int g = 0; g < 2; g++) {
                    uint32_t q0, q1, q2, q3;
                    ldsm4(q0, q1, q2, q3, stg + 8192 + bRow + (uint32_t)(g * 1024) + cb);
                    bf[2 * g][0] = q0; bf[2 * g][1] = q1;
                    bf[2 * g + 1][0] = q2; bf[2 * g + 1][1] = q3;
                }
#pragma unroll
                for (int mt = 0; mt < 4; mt++)
#pragma unroll
                    for (int ng = 0; ng < 4; ng++) mma_f16(acc[mt][ng], a[mt], bf[ng]);
            }
        }
    }

    int cr = lane >> 2, cc = (lane & 3) << 1;
#pragma unroll
    for (int mt = 0; mt < 4; mt++)
#pragma unroll
        for (int ng = 0; ng < 4; ng++) {
            int row = row0 + wm + (mt << 4) + cr;
            int col = col0 + wn + (ng << 3) + cc;
            if (col < N) {
                *reinterpret_cast<float2*>(C + (size_t)row * ldc + col) =
                    make_float2(acc[mt][ng][0], acc[mt][ng][1]);
                *reinterpret_cast<float2*>(C + (size_t)(row + 8) * ldc + col) =
                    make_float2(acc[mt][ng][2], acc[mt][ng][3]);
            }
        }
}

// ================= xdbl split-K reduce + scatter (knq + dtl convert/pad) =================
__global__ __launch_bounds__(256)
void xdbl_reduce_kernel() {
    int i = blockIdx.x * 256 + threadIdx.x;
    if (i >= Mz * 96) return;
    int r = i / 96, c = i - r * 96;
    if (c < 48) {
        float v = 0.f;
#pragma unroll
        for (int z = 0; z < NSPK; z++) v += g_xdp[(size_t)z * Mz * XDB + (size_t)r * XDB + c];
        g_dtl_c[(size_t)r * RKP + c] = __float2half_rn(v);
    } else if (c < 64) {
        g_dtl_c[(size_t)r * RKP + c] = __float2half_rn(0.f);
    } else if (c < 80) {
        int sc = c - 16;
        float v = 0.f;
#pragma unroll
        for (int z = 0; z < NSPK; z++) v += g_xdp[(size_t)z * Mz * XDB + (size_t)r * XDB + sc];
        g_knq[(size_t)r * 48 + (c - 64)] = v;
        g_knq[(size_t)r * 48 + 16 + (c - 64)] = v * v;
    } else {
        int sc = c - 16;
        float v = 0.f;
#pragma unroll
        for (int z = 0; z < NSPK; z++) v += g_xdp[(size_t)z * Mz * XDB + (size_t)r * XDB + sc];
        g_knq[(size_t)r * 48 + 32 + (c - 80)] = v;
    }
}

// ================= depthwise causal conv (k=4) + SiLU -> fp32 + fp16 =================
__global__ __launch_bounds__(128)
void conv_silu_kernel(const float* __restrict__ conv_w,
                      const float* __restrict__ conv_b) {
    int d = blockIdx.x * 128 + threadIdx.x;
    int t0 = blockIdx.y * 16;
    int b = blockIdx.z;
    size_t base = (size_t)b * Lz;

    float xv[19];
#pragma unroll
    for (int i = 0; i < 19; i++) {
        int t = t0 - 3 + i;
        xv[i] = (t >= 0) ? g_xz[(base + t) * DI2 + d] : 0.f;
    }
    float w0 = conv_w[d * 4 + 0], w1 = conv_w[d * 4 + 1];
    float w2 = conv_w[d * 4 + 2], w3 = conv_w[d * 4 + 3];
    float bias = conv_b[d];
#pragma unroll
    for (int j = 0; j < 16; j++) {
        float a = fmaf(w0, xv[j], fmaf(w1, xv[j + 1], fmaf(w2, xv[j + 2], fmaf(w3, xv[j + 3], bias))));
        float s = a / (1.f + __expf(-a));
        size_t idx = (base + t0 + j) * DI + d;
        g_xact[idx] = s;
        g_xact_c[idx] = __float2half_rn(s);
    }
}

// ================= prep: rank-1 Newton-Schulz closed form + fp32 pack =================
__global__ __launch_bounds__(256)
void prep_kernel(const float* __restrict__ dt_bias, const float* __restrict__ Dv) {
    int m = blockIdx.x;
    int tid = threadIdx.x;
    __shared__ float s_ksq[16];
    __shared__ float s_kk, s_su;
    __shared__ float red[8];

    if (tid < 16) s_ksq[tid] = g_knq[(size_t)m * 48 + 16 + tid];
    __syncthreads();
    if (tid == 0) {
        float kk = 0.f;
#pragma unroll
        for (int n = 0; n < 16; n++) kk += s_ksq[n];
        s_kk = kk;
    }
    __syncthreads();
    float kk = s_kk;

    float u[6], dtt[6], xv[6];
    float su = 0.f;
#pragma unroll
    for (int i = 0; i < 6; i++) {
        int d = tid + i * 256;
        float dtr = g_dt[(size_t)m * DI + d] + dt_bias[d];
        float s0 = 1.f / (1.f + __expf(-dtr));
        float dv = s0 / (1.f + s0 * kk);
        float x = g_xact[(size_t)m * DI + d];
        float uu = dv * x;
        su += uu * uu;
        u[i] = uu; dtt[i] = dv; xv[i] = x;
    }
#pragma unroll
    for (int off = 16; off > 0; off >>= 1) su += __shfl_xor_sync(0xffffffffu, su, off);
    if ((tid & 31) == 0) red[tid >> 5] = su;
    __syncthreads();
    if (tid == 0) {
        float s = 0.f;
#pragma unroll
        for (int i = 0; i < 8; i++) s += red[i];
        s_su = s;
    }
    __syncthreads();

    float Nn = sqrtf(s_su * kk);
    float t1 = 1.f / (Nn + 1e-7f);
    float nt = Nn * t1;
    float nt2 = nt * nt;
    float s = t1 * (3.4445f + nt2 * (-4.7750f + 2.0315f * nt2));

#pragma unroll
    for (int i = 0; i < 6; i++) {
        int d = tid + i * 256;
        float z = g_xz[(size_t)m * DI2 + DI + d];
        float zs = z / (1.f + __expf(-z));
        g_pack[(size_t)m * DI + d] = make_float4(s * u[i], dtt[i], Dv[d] * xv[i], zs);
    }
}

// ================= scan: 4-way n-split; 16-step windows; 4-stage cp.async =================
__global__ __launch_bounds__(64)
void scan_kernel() {
    __shared__ __align__(16) float4 s_pack[4][256];   // [stage][s*16 + dd], 16 steps
    __shared__ __align__(16) float  s_knq[4][768];    // [stage][s*48 + j],  16 steps
    int tid = threadIdx.x;
    int ng = tid & 3, dd = tid >> 2;
    int d0 = blockIdx.x << 4;
    int d = d0 + dd;
    int b = blockIdx.y;
    size_t mbase = (size_t)b * Lz;
    const int NW = Lz / 16;   // 64 windows of 16 steps

    uint32_t spack = (uint32_t)__cvta_generic_to_shared(s_pack);
    uint32_t sknq  = (uint32_t)__cvta_generic_to_shared(s_knq);
    const float* knq_src = g_knq + mbase * 48;

    auto issue = [&](int w) {
        uint32_t st = (uint32_t)(w & 3);
        // pack: 256 float4 chunks -> 4 per thread (uniform)
#pragma unroll
        for (int i = 0; i < 4; i++) {
            int c = tid + (i << 6);
            int s = c >> 4, dd2 = c & 15;
            const float4* src = &g_pack[(mbase + ((size_t)w << 4) + s) * DI + d0 + dd2];
            cpa16u(spack + st * 4096 + (uint32_t)(c << 4), src);
        }
        // knq: 768 floats = 192 chunks -> 3 per thread (uniform)
#pragma unroll
        for (int i = 0; i < 3; i++) {
            int c = tid + (i << 6);
            const float* src = knq_src + (((size_t)w << 4) * 48) + (c << 2);
            cpa16u(sknq + st * 3072 + (uint32_t)(c << 4), src);
        }
    };

    issue(0); cp_commit();
    issue(1); cp_commit();
    issue(2); cp_commit();

    float v0 = 0.f, v1 = 0.f, v2 = 0.f, v3 = 0.f;
    float h0 = 0.f, h1 = 0.f, h2 = 0.f, h3 = 0.f;

    for (int w = 0; w < NW; w++) {
        asm volatile("cp.async.wait_group 2;");
        __syncthreads();
        if (w + 3 < NW) issue(w + 3);
        cp_commit();

        int st = w & 3;
        float ys[16];
#pragma unroll
        for (int s = 0; s < 16; s++) {
            float4 p = s_pack[st][(s << 4) + dd];
            const float* kb = &s_knq[st][s * 48 + (ng << 2)];
            float4 kv = *reinterpret_cast<const float4*>(kb);
            float4 k2 = *reinterpret_cast<const float4*>(kb + 16);
            float4 qv = *reinterpret_cast<const float4*>(kb + 32);
            v0 = fmaf(0.9f, v0, p.x * kv.x); h0 = fmaf(fmaf(-p.y, k2.x, 1.f), h0, v0);
            v1 = fmaf(0.9f, v1, p.x * kv.y); h1 = fmaf(fmaf(-p.y, k2.y, 1.f), h1, v1);
            v2 = fmaf(0.9f, v2, p.x * kv.z); h2 = fmaf(fmaf(-p.y, k2.z, 1.f), h2, v2);
            v3 = fmaf(0.9f, v3, p.x * kv.w); h3 = fmaf(fmaf(-p.y, k2.w, 1.f), h3, v3);
            ys[s] = fmaf(h0, qv.x, fmaf(h1, qv.y, fmaf(h2, qv.z, h3 * qv.w)));
        }
#pragma unroll
        for (int s = 0; s < 16; s++) ys[s] += __shfl_xor_sync(0xffffffffu, ys[s], 1);
#pragma unroll
        for (int s = 0; s < 16; s++) ys[s] += __shfl_xor_sync(0xffffffffu, ys[s], 2);
        if (ng == 0) {
#pragma unroll
            for (int s = 0; s < 16; s++) {
                float4 p = s_pack[st][(s << 4) + dd];
                size_t m = mbase + ((size_t)w << 4) + s;
                float yo = (ys[s] + p.z) * p.w;
                g_yg_c[m * DI + d] = __float2half_rn(yo);
            }
        }
    }
}

// ================= launch =================
extern "C" void kernel_launch(void* const* d_in, const int* in_sizes, int n_in,
                              void* d_out, int out_size) {
    const float* hs        = (const float*)d_in[0];
    const float* in_proj_w = (const float*)d_in[1];
    const float* conv_w    = (const float*)d_in[2];
    const float* conv_b    = (const float*)d_in[3];
    const float* x_proj_w  = (const float*)d_in[4];
    const float* dt_head_w = (const float*)d_in[5];
    const float* dt_head_b = (const float*)d_in[6];
    const float* out_proj  = (const float*)d_in[7];
    const float* Dv        = (const float*)d_in[8];
    float* out = (float*)d_out;

    static bool attr_set = false;
    if (!attr_set) {
        cudaFuncSetAttribute(mma_gemm, cudaFuncAttributeMaxDynamicSharedMemorySize, 49152);
        attr_set = true;
    }
    const int SMEMB = 49152;   // 3 stages x 16KB

    void *p_xz, *p_dt, *p_xdp;
    cudaGetSymbolAddress(&p_xz, g_xz);
    cudaGetSymbolAddress(&p_dt, g_dt);
    cudaGetSymbolAddress(&p_xdp, g_xdp);
    void *hs_c, *ipw_c, *xact_c, *xpw_c, *dtl_c, *dthw_c, *yg_c, *opw_c;
    cudaGetSymbolAddress(&hs_c, g_hs_c);
    cudaGetSymbolAddress(&ipw_c, g_ipw_c);
    cudaGetSymbolAddress(&xact_c, g_xact_c);
    cudaGetSymbolAddress(&xpw_c, g_xpw_c);
    cudaGetSymbolAddress(&dtl_c, g_dtl_c);
    cudaGetSymbolAddress(&dthw_c, g_dthw_c);
    cudaGetSymbolAddress(&yg_c, g_yg_c);
    cudaGetSymbolAddress(&opw_c, g_opw_c);

    // 0) fused fp16 converts: hs, in_proj_w, x_proj_w, out_proj, dt_head_w(pad)
    {
        int n0 = Mz * DM, n1 = DI2 * DM, n2 = XDB * DI, n3 = DM * DI, n4 = DI * RKP;
        int g0 = (n0 + 255) / 256, g1 = (n1 + 255) / 256, g2 = (n2 + 255) / 256,
            g3 = (n3 + 255) / 256, g4 = (n4 + 255) / 256;
        cvt5_kernel<<<g0 + g1 + g2 + g3 + g4, 256>>>(
            hs, (__half*)hs_c, n0, g0,
            in_proj_w, (__half*)ipw_c, n1, g0 + g1,
            x_proj_w, (__half*)xpw_c, n2, g0 + g1 + g2,
            out_proj, (__half*)opw_c, n3, g0 + g1 + g2 + g3,
            dt_head_w, (__half*)dthw_c, n4);
    }

    // 1) xz = hs @ in_proj^T  (2048 x 3072, K=768)
    mma_gemm<<<dim3(DI2 / 128, Mz / 128, 1), 256, SMEMB>>>(
        (const __half*)hs_c, (const __half*)ipw_c, (float*)p_xz, DI2, DM, DM, DI2, 0);
    // 2) conv + SiLU
    conv_silu_kernel<<<dim3(DI / 128, Lz / 16, Bz), 128>>>(conv_w, conv_b);
    // 3) x_dbl split-K partials (16-way)
    mma_gemm<<<dim3(1, Mz / 128, NSPK), 256, SMEMB>>>(
        (const __half*)xact_c, (const __half*)xpw_c, (float*)p_xdp,
        XDB, DI / NSPK, DI, XDB, Mz * XDB);
    // 3b) reduce -> knq + dtl
    xdbl_reduce_kernel<<<(Mz * 96 + 255) / 256, 256>>>();
    // 4) dt = dt_low @ dt_head^T  (K=64 padded)
    mma_gemm<<<dim3(DI / 128, Mz / 128, 1), 256, SMEMB>>>(
        (const __half*)dtl_c, (const __half*)dthw_c, (float*)p_dt, DI, RKP, RKP, DI, 0);
    // 5) prep
    prep_kernel<<<Mz, 256>>>(dt_head_b, Dv);
    // 6) scan (16-step windows)
    scan_kernel<<<dim3(DI / 16, Bz), 64>>>();
    // 7) out = yg @ out_proj^T
    mma_gemm<<<dim3(DM / 128, Mz / 128, 1), 256, SMEMB>>>(
        (const __half*)yg_c, (const __half*)opw_c, out, DM, DI, DI, DM, 0);
}